// round 9
// baseline (speedup 1.0000x reference)
#include <cuda_runtime.h>
#include <cuda_fp16.h>
#include <cstdint>

#define INN   4096
#define OUTN  4096
#define BATCH 8192
#define KSEL  64

// Dense fp16 weight + fp16 activations (device-global scratch; no runtime alloc).
__device__ __align__(16) __half g_W[(size_t)OUTN * INN];   // 32 MB
__device__ __align__(16) __half g_X[(size_t)BATCH * INN];  // 64 MB

// ===========================================================================
// Helpers
// ===========================================================================
__device__ __forceinline__ uint32_t smem_u32(const void* p) {
    uint32_t a;
    asm("{ .reg .u64 t; cvta.to.shared.u64 t, %1; cvt.u32.u64 %0, t; }" : "=r"(a) : "l"(p));
    return a;
}
__device__ __forceinline__ void cp16(uint32_t dst, const void* src) {
    asm volatile("cp.async.cg.shared.global [%0], [%1], 16;" :: "r"(dst), "l"(src));
}
__device__ __forceinline__ void ldmat_x4(uint32_t& r0, uint32_t& r1, uint32_t& r2,
                                         uint32_t& r3, uint32_t addr) {
    asm volatile("ldmatrix.sync.aligned.m8n8.x4.shared.b16 {%0,%1,%2,%3}, [%4];"
                 : "=r"(r0), "=r"(r1), "=r"(r2), "=r"(r3) : "r"(addr));
}
__device__ __forceinline__ void mma16816(float* c, const uint32_t* a, const uint32_t* b) {
    asm volatile(
        "mma.sync.aligned.m16n8k16.row.col.f32.f16.f16.f32 "
        "{%0,%1,%2,%3}, {%4,%5,%6,%7}, {%8,%9}, {%0,%1,%2,%3};"
        : "+f"(c[0]), "+f"(c[1]), "+f"(c[2]), "+f"(c[3])
        : "r"(a[0]), "r"(a[1]), "r"(a[2]), "r"(a[3]), "r"(b[0]), "r"(b[1]));
}

#define MBARRIER_INIT(addr, cnt) \
    asm volatile("mbarrier.init.shared.b64 [%0], %1;" :: "r"(addr), "r"((uint32_t)(cnt)) : "memory")
#define MBARRIER_ARRIVE(addr) \
    asm volatile("mbarrier.arrive.shared.b64 _, [%0];" :: "r"(addr) : "memory")
#define CP_MBAR_ARRIVE(addr) \
    asm volatile("cp.async.mbarrier.arrive.noinc.shared.b64 [%0];" :: "r"(addr) : "memory")
#define MBARRIER_WAIT_PARITY(addr, par) do {                                          \
    uint32_t _m = (addr); uint32_t _p = (par); uint32_t _d;                           \
    asm volatile("{ .reg .pred p; mbarrier.try_wait.parity.acquire.cta.shared::cta.b64 p, [%1], %2; selp.b32 %0,1,0,p; }" \
        : "=r"(_d) : "r"(_m), "r"(_p) : "memory");                                    \
    if (!_d) {                                                                        \
        asm volatile("{ .reg .pred P1; WL_%=: mbarrier.try_wait.parity.acquire.cta.shared::cta.b64 P1, [%0], %1, 0x989680; @P1 bra.uni WD_%=; bra.uni WL_%=; WD_%=: }" \
            :: "r"(_m), "r"(_p) : "memory");                                          \
    }                                                                                 \
} while (0)

// Monotonic float -> uint32 key (order-preserving), and its inverse.
__device__ __forceinline__ uint32_t fkey(float f) {
    uint32_t u = __float_as_uint(f);
    return (u & 0x80000000u) ? ~u : (u | 0x80000000u);
}
__device__ __forceinline__ float fkey_inv(uint32_t k) {
    uint32_t u = (k & 0x80000000u) ? (k & 0x7FFFFFFFu) : ~k;
    return __uint_as_float(u);
}

// ===========================================================================
// Kernel A (fused): blocks [0, OUTN) build one weight row each via 32-bit
// radix-select + explicit tie ranking (matches jax.lax.top_k exactly);
// blocks [OUTN, OUTN+CONV_BLKS) convert a chunk of x fp32 -> fp16.
// ===========================================================================
#define CONV_BLKS 4096

__global__ void __launch_bounds__(256) prep_kernel(const float* __restrict__ pre_w,
                                                   const float* __restrict__ sign_matrix,
                                                   const float* __restrict__ x) {
    const int tid = threadIdx.x;

    if (blockIdx.x >= OUTN) {
        // ---- convert x chunk ----
        int cb = blockIdx.x - OUTN;
        const float4* x4 = reinterpret_cast<const float4*>(x);
        __half2* dst = reinterpret_cast<__half2*>(g_X);
#pragma unroll
        for (int i = 0; i < 8; i++) {
            size_t v = (size_t)cb * 2048 + i * 256 + tid;
            float4 d = x4[v];
            dst[v * 2 + 0] = __floats2half2_rn(d.x, d.y);
            dst[v * 2 + 1] = __floats2half2_rn(d.z, d.w);
        }
        return;
    }

    __shared__ int s_warp[8];
    const int row  = blockIdx.x;
    const int lane = tid & 31;
    const int wid  = tid >> 5;

    const float4* w4 = reinterpret_cast<const float4*>(pre_w + (size_t)row * INN);

    uint32_t keys[16];
#pragma unroll
    for (int j = 0; j < 4; j++) {
        float4 v = w4[tid * 4 + j];
        keys[j * 4 + 0] = fkey(v.x);
        keys[j * 4 + 1] = fkey(v.y);
        keys[j * 4 + 2] = fkey(v.z);
        keys[j * 4 + 3] = fkey(v.w);
    }

    // Binary search: largest P with count(keys >= P) >= KSEL.
    uint32_t P = 0;
#pragma unroll 1
    for (int bit = 31; bit >= 0; bit--) {
        uint32_t trial = P | (1u << bit);
        unsigned c = 0;
#pragma unroll
        for (int e = 0; e < 16; e++) c += (keys[e] >= trial);
        c = __reduce_add_sync(0xFFFFFFFFu, c);
        if (lane == 0) s_warp[wid] = (int)c;
        __syncthreads();
        int total = s_warp[0] + s_warp[1] + s_warp[2] + s_warp[3]
                  + s_warp[4] + s_warp[5] + s_warp[6] + s_warp[7];
        if (total >= KSEL) P = trial;
        __syncthreads();
    }

    // Count strictly-greater and ties.
    unsigned gt = 0, eq = 0;
#pragma unroll
    for (int e = 0; e < 16; e++) {
        gt += (keys[e] > P);
        eq += (keys[e] == P);
    }
    unsigned packed = __reduce_add_sync(0xFFFFFFFFu, (gt << 16) | eq);
    if (lane == 0) s_warp[wid] = (int)packed;
    __syncthreads();
    unsigned tot = (unsigned)(s_warp[0] + s_warp[1] + s_warp[2] + s_warp[3]
                            + s_warp[4] + s_warp[5] + s_warp[6] + s_warp[7]);
    const int total_gt = (int)(tot >> 16);
    const int total_eq = (int)(tot & 0xFFFFu);
    const int sel_ties = KSEL - total_gt;
    const bool common = (total_eq == sel_ties);

    int offset = 0;
    if (!common) {
        // Rank ties by global element index (thread-contiguous layout => tid order).
        __syncthreads();
        int v = (int)eq;
#pragma unroll
        for (int off = 1; off < 32; off <<= 1) {
            int n = __shfl_up_sync(0xFFFFFFFFu, v, off);
            if (lane >= off) v += n;
        }
        int excl = v - (int)eq;
        if (lane == 31) s_warp[wid] = v;
        __syncthreads();
        int wpre = 0;
#pragma unroll
        for (int w = 0; w < 8; w++) wpre += (w < wid) ? s_warp[w] : 0;
        offset = wpre + excl;
    }

    // Emit dense fp16 row.
    const float4* s4 = reinterpret_cast<const float4*>(sign_matrix + (size_t)row * INN);
    uint64_t* dst = reinterpret_cast<uint64_t*>(g_W + (size_t)row * INN);
    int cnt = 0;
#pragma unroll
    for (int j = 0; j < 4; j++) {
        float4 sg = s4[tid * 4 + j];
        const float* sp = reinterpret_cast<const float*>(&sg);
        __half h[4];
#pragma unroll
        for (int e = 0; e < 4; e++) {
            uint32_t k = keys[j * 4 + e];
            bool sel = false;
            if (k > P) sel = true;
            else if (k == P) {
                sel = common ? true : ((offset + cnt) < sel_ties);
                cnt++;
            }
            float f = fkey_inv(k);
            h[e] = __float2half(sel ? expf(f) * sp[e] : 0.0f);
        }
        dst[tid * 4 + j] = *reinterpret_cast<const uint64_t*>(h);
    }
}

// ===========================================================================
// Kernel C: mma.sync GEMM, 2 CTAs per SM. out[B,OUT] = g_X @ g_W^T.
// Block tile 128x128, BK=64, 3-stage cp.async mbarrier ring; 128 threads =
// 4 warps (2x2), warp tile 64x64, fragments double-buffered across k-steps.
// full[s]: count 128 (cp.async.mbarrier.arrive.noinc per thread).
// empty[s]: count 4 (one arrive per warp after its last ldsm of the stage).
// Smem rows 144 B (128 data + 16 pad) => conflict-free ldmatrix.
// Two independent CTAs per SM decorrelate stage-boundary stalls.
// ===========================================================================
#define BM 128
#define BN 128
#define BK 64
#define NST 3
#define ROWB 144
#define A_STAGE (BM * ROWB)                 // 18432
#define B_STAGE (BN * ROWB)                 // 18432
#define STAGE_BYTES (A_STAGE + B_STAGE)     // 36864
#define SMEM_TOTAL (1024 + NST * STAGE_BYTES)   // 111616
#define NITER (INN / BK)                    // 64
#define GT 128                               // threads

__device__ __forceinline__ void load_stage(int s, int slot, int tid, int m0, int n0,
                                           uint32_t tile0) {
    uint32_t aS = tile0 + (uint32_t)slot * STAGE_BYTES;
    uint32_t bS = aS + A_STAGE;
    const __half* aG = g_X + (size_t)m0 * INN + s * BK;
    const __half* bG = g_W + (size_t)n0 * INN + s * BK;
#pragma unroll
    for (int i = 0; i < 8; i++) {            // A: 128 rows x 8 chunks of 16 B
        int t = tid + i * GT;
        int r = t >> 3, c = t & 7;
        cp16(aS + r * ROWB + c * 16, aG + (size_t)r * INN + c * 8);
    }
#pragma unroll
    for (int i = 0; i < 8; i++) {            // B: 128 rows x 8 chunks of 16 B
        int t = tid + i * GT;
        int r = t >> 3, c = t & 7;
        cp16(bS + r * ROWB + c * 16, bG + (size_t)r * INN + c * 8);
    }
}

__device__ __forceinline__ void load_frags(uint32_t aS, uint32_t bS, uint32_t kb,
                                           uint32_t a_row, uint32_t a_kof,
                                           uint32_t b_row, uint32_t b_kof,
                                           uint32_t afr[4][4], uint32_t bfr[8][2]) {
#pragma unroll
    for (int mt = 0; mt < 4; mt++)
        ldmat_x4(afr[mt][0], afr[mt][1], afr[mt][2], afr[mt][3],
                 aS + (a_row + mt * 16) * ROWB + kb + a_kof);
#pragma unroll
    for (int p = 0; p < 4; p++) {
        uint32_t r0, r1, r2, r3;
        ldmat_x4(r0, r1, r2, r3, bS + (b_row + p * 16) * ROWB + kb + b_kof);
        bfr[2 * p][0] = r0;     bfr[2 * p][1] = r1;
        bfr[2 * p + 1][0] = r2; bfr[2 * p + 1][1] = r3;
    }
}

__global__ void __launch_bounds__(GT, 2) gemm_kernel(float* __restrict__ out) {
    extern __shared__ char smem[];
    const uint32_t sbase = smem_u32(smem);
    const int tid  = threadIdx.x;
    const int lane = tid & 31;
    const int wid  = tid >> 5;
    const int m0 = blockIdx.x * BM;
    const int n0 = blockIdx.y * BN;
    const int wm = (wid & 1) * 64;
    const int wn = (wid >> 1) * 64;

    const uint32_t TILE0 = sbase + 1024;
#define FULLB(i)  (sbase + (uint32_t)(i) * 8)
#define EMPTYB(i) (sbase + 32 + (uint32_t)(i) * 8)

    if (tid == 0) {
#pragma unroll
        for (int i = 0; i < NST; i++) {
            MBARRIER_INIT(FULLB(i), GT);
            MBARRIER_INIT(EMPTYB(i), 4);
        }
    }
    __syncthreads();

    float acc[4][8][4];
#pragma unroll
    for (int mt = 0; mt < 4; mt++)
#pragma unroll
        for (int nt = 0; nt < 8; nt++)
#pragma unroll
            for (int i = 0; i < 4; i++) acc[mt][nt][i] = 0.0f;

    // Producer cursor (starts phase 1: first NST empty-waits pass immediately).
    int p_slot = 0, p_phase = 1;
    // Consumer cursor.
    int c_slot = 0, c_phase = 0;

    // Prologue: stages 0..NST-2 in flight (empty-waits would pass; skipped).
#pragma unroll
    for (int s = 0; s < NST - 1; s++) {
        load_stage(s, p_slot, tid, m0, n0, TILE0);
        CP_MBAR_ARRIVE(FULLB(p_slot));
        if (++p_slot == NST) { p_slot = 0; p_phase ^= 1; }
    }

    const uint32_t a_row = wm + (lane & 15);
    const uint32_t a_kof = (uint32_t)(lane >> 4) * 16;
    const uint32_t b_row = wn + (lane & 7) + ((lane >> 4) << 3);
    const uint32_t b_kof = (uint32_t)((lane >> 3) & 1) * 16;

    uint32_t afr[2][4][4], bfr[2][8][2];

#pragma unroll 1
    for (int it = 0; it < NITER; it++) {
        // Produce stage it + NST - 1.
        int ps = it + NST - 1;
        if (ps < NITER) {
            MBARRIER_WAIT_PARITY(EMPTYB(p_slot), (uint32_t)p_phase);
            load_stage(ps, p_slot, tid, m0, n0, TILE0);
            CP_MBAR_ARRIVE(FULLB(p_slot));
            if (++p_slot == NST) { p_slot = 0; p_phase ^= 1; }
        }

        // Consume stage it.
        MBARRIER_WAIT_PARITY(FULLB(c_slot), (uint32_t)c_phase);

        uint32_t aS = TILE0 + (uint32_t)c_slot * STAGE_BYTES;
        uint32_t bS = aS + A_STAGE;

        load_frags(aS, bS, 0, a_row, a_kof, b_row, b_kof, afr[0], bfr[0]);
#pragma unroll
        for (int ks = 0; ks < 4; ks++) {
            if (ks < 3)
                load_frags(aS, bS, (uint32_t)(ks + 1) * 32, a_row, a_kof, b_row, b_kof,
                           afr[(ks + 1) & 1], bfr[(ks + 1) & 1]);
            if (ks == 2 && lane == 0) {
                // All of this warp's smem reads for this stage are issued
                // (ldmatrix is warp-synchronous) — release the slot.
                MBARRIER_ARRIVE(EMPTYB(c_slot));
            }
            uint32_t (*af)[4] = afr[ks & 1];
            uint32_t (*bf)[2] = bfr[ks & 1];
#pragma unroll
            for (int mt = 0; mt < 4; mt++)
#pragma unroll
                for (int nt = 0; nt < 8; nt++)
                    mma16816(acc[mt][nt], af[mt], bf[nt]);
        }
        if (++c_slot == NST) { c_slot = 0; c_phase ^= 1; }
    }

    // Epilogue.
    const int er = lane >> 2;
    const int ec = (lane & 3) * 2;
#pragma unroll
    for (int mt = 0; mt < 4; mt++) {
        int m = m0 + wm + mt * 16 + er;
#pragma unroll
        for (int nt = 0; nt < 8; nt++) {
            int n = n0 + wn + nt * 8 + ec;
            float2* p0 = reinterpret_cast<float2*>(out + (size_t)m * OUTN + n);
            float2* p1 = reinterpret_cast<float2*>(out + (size_t)(m + 8) * OUTN + n);
            *p0 = make_float2(acc[mt][nt][0], acc[mt][nt][1]);
            *p1 = make_float2(acc[mt][nt][2], acc[mt][nt][3]);
        }
    }
}

// ===========================================================================
extern "C" void kernel_launch(void* const* d_in, const int* in_sizes, int n_in,
                              void* d_out, int out_size) {
    const float* x      = (const float*)d_in[0];
    const float* pre_w  = (const float*)d_in[1];
    const float* sign_m = (const float*)d_in[2];
    float* out = (float*)d_out;

    cudaFuncSetAttribute(gemm_kernel, cudaFuncAttributeMaxDynamicSharedMemorySize, SMEM_TOTAL);

    prep_kernel<<<OUTN + CONV_BLKS, 256>>>(pre_w, sign_m, x);
    gemm_kernel<<<dim3(BATCH / BM, OUTN / BN), GT, SMEM_TOTAL>>>(out);
}

// round 10
// speedup vs baseline: 1.0810x; 1.0810x over previous
#include <cuda_runtime.h>
#include <cuda_fp16.h>
#include <cstdint>

#define INN   4096
#define OUTN  4096
#define BATCH 8192
#define KSEL  64

// Dense fp16 weight + fp16 activations (device-global scratch; no runtime alloc).
__device__ __align__(16) __half g_W[(size_t)OUTN * INN];   // 32 MB
__device__ __align__(16) __half g_X[(size_t)BATCH * INN];  // 64 MB

// ===========================================================================
// Helpers
// ===========================================================================
__device__ __forceinline__ uint32_t smem_u32(const void* p) {
    uint32_t a;
    asm("{ .reg .u64 t; cvta.to.shared.u64 t, %1; cvt.u32.u64 %0, t; }" : "=r"(a) : "l"(p));
    return a;
}
__device__ __forceinline__ void cp16(uint32_t dst, const void* src) {
    asm volatile("cp.async.cg.shared.global [%0], [%1], 16;" :: "r"(dst), "l"(src));
}
__device__ __forceinline__ void ldmat_x4(uint32_t& r0, uint32_t& r1, uint32_t& r2,
                                         uint32_t& r3, uint32_t addr) {
    asm volatile("ldmatrix.sync.aligned.m8n8.x4.shared.b16 {%0,%1,%2,%3}, [%4];"
                 : "=r"(r0), "=r"(r1), "=r"(r2), "=r"(r3) : "r"(addr));
}
__device__ __forceinline__ void mma16816(float* c, const uint32_t* a, const uint32_t* b) {
    asm volatile(
        "mma.sync.aligned.m16n8k16.row.col.f32.f16.f16.f32 "
        "{%0,%1,%2,%3}, {%4,%5,%6,%7}, {%8,%9}, {%0,%1,%2,%3};"
        : "+f"(c[0]), "+f"(c[1]), "+f"(c[2]), "+f"(c[3])
        : "r"(a[0]), "r"(a[1]), "r"(a[2]), "r"(a[3]), "r"(b[0]), "r"(b[1]));
}

#define MBARRIER_INIT(addr, cnt) \
    asm volatile("mbarrier.init.shared.b64 [%0], %1;" :: "r"(addr), "r"((uint32_t)(cnt)) : "memory")
#define MBARRIER_ARRIVE(addr) \
    asm volatile("mbarrier.arrive.shared.b64 _, [%0];" :: "r"(addr) : "memory")
#define CP_MBAR_ARRIVE(addr) \
    asm volatile("cp.async.mbarrier.arrive.noinc.shared.b64 [%0];" :: "r"(addr) : "memory")
#define MBARRIER_WAIT_PARITY(addr, par) do {                                          \
    uint32_t _m = (addr); uint32_t _p = (par); uint32_t _d;                           \
    asm volatile("{ .reg .pred p; mbarrier.try_wait.parity.acquire.cta.shared::cta.b64 p, [%1], %2; selp.b32 %0,1,0,p; }" \
        : "=r"(_d) : "r"(_m), "r"(_p) : "memory");                                    \
    if (!_d) {                                                                        \
        asm volatile("{ .reg .pred P1; WL_%=: mbarrier.try_wait.parity.acquire.cta.shared::cta.b64 P1, [%0], %1, 0x989680; @P1 bra.uni WD_%=; bra.uni WL_%=; WD_%=: }" \
            :: "r"(_m), "r"(_p) : "memory");                                          \
    }                                                                                 \
} while (0)

// Monotonic float -> uint32 key (order-preserving), and its inverse.
__device__ __forceinline__ uint32_t fkey(float f) {
    uint32_t u = __float_as_uint(f);
    return (u & 0x80000000u) ? ~u : (u | 0x80000000u);
}
__device__ __forceinline__ float fkey_inv(uint32_t k) {
    uint32_t u = (k & 0x80000000u) ? (k & 0x7FFFFFFFu) : ~k;
    return __uint_as_float(u);
}

// ===========================================================================
// Kernel A (fused): blocks [0, OUTN) build one weight row each via 32-bit
// radix-select + explicit tie ranking (matches jax.lax.top_k exactly);
// blocks [OUTN, OUTN+CONV_BLKS) convert a chunk of x fp32 -> fp16.
// ===========================================================================
#define CONV_BLKS 4096

__global__ void __launch_bounds__(256) prep_kernel(const float* __restrict__ pre_w,
                                                   const float* __restrict__ sign_matrix,
                                                   const float* __restrict__ x) {
    const int tid = threadIdx.x;

    if (blockIdx.x >= OUTN) {
        // ---- convert x chunk ----
        int cb = blockIdx.x - OUTN;
        const float4* x4 = reinterpret_cast<const float4*>(x);
        __half2* dst = reinterpret_cast<__half2*>(g_X);
#pragma unroll
        for (int i = 0; i < 8; i++) {
            size_t v = (size_t)cb * 2048 + i * 256 + tid;
            float4 d = x4[v];
            dst[v * 2 + 0] = __floats2half2_rn(d.x, d.y);
            dst[v * 2 + 1] = __floats2half2_rn(d.z, d.w);
        }
        return;
    }

    __shared__ int s_warp[8];
    const int row  = blockIdx.x;
    const int lane = tid & 31;
    const int wid  = tid >> 5;

    const float4* w4 = reinterpret_cast<const float4*>(pre_w + (size_t)row * INN);

    uint32_t keys[16];
#pragma unroll
    for (int j = 0; j < 4; j++) {
        float4 v = w4[tid * 4 + j];
        keys[j * 4 + 0] = fkey(v.x);
        keys[j * 4 + 1] = fkey(v.y);
        keys[j * 4 + 2] = fkey(v.z);
        keys[j * 4 + 3] = fkey(v.w);
    }

    // Binary search: largest P with count(keys >= P) >= KSEL.
    uint32_t P = 0;
#pragma unroll 1
    for (int bit = 31; bit >= 0; bit--) {
        uint32_t trial = P | (1u << bit);
        unsigned c = 0;
#pragma unroll
        for (int e = 0; e < 16; e++) c += (keys[e] >= trial);
        c = __reduce_add_sync(0xFFFFFFFFu, c);
        if (lane == 0) s_warp[wid] = (int)c;
        __syncthreads();
        int total = s_warp[0] + s_warp[1] + s_warp[2] + s_warp[3]
                  + s_warp[4] + s_warp[5] + s_warp[6] + s_warp[7];
        if (total >= KSEL) P = trial;
        __syncthreads();
    }

    // Count strictly-greater and ties.
    unsigned gt = 0, eq = 0;
#pragma unroll
    for (int e = 0; e < 16; e++) {
        gt += (keys[e] > P);
        eq += (keys[e] == P);
    }
    unsigned packed = __reduce_add_sync(0xFFFFFFFFu, (gt << 16) | eq);
    if (lane == 0) s_warp[wid] = (int)packed;
    __syncthreads();
    unsigned tot = (unsigned)(s_warp[0] + s_warp[1] + s_warp[2] + s_warp[3]
                            + s_warp[4] + s_warp[5] + s_warp[6] + s_warp[7]);
    const int total_gt = (int)(tot >> 16);
    const int total_eq = (int)(tot & 0xFFFFu);
    const int sel_ties = KSEL - total_gt;
    const bool common = (total_eq == sel_ties);

    int offset = 0;
    if (!common) {
        // Rank ties by global element index (thread-contiguous layout => tid order).
        __syncthreads();
        int v = (int)eq;
#pragma unroll
        for (int off = 1; off < 32; off <<= 1) {
            int n = __shfl_up_sync(0xFFFFFFFFu, v, off);
            if (lane >= off) v += n;
        }
        int excl = v - (int)eq;
        if (lane == 31) s_warp[wid] = v;
        __syncthreads();
        int wpre = 0;
#pragma unroll
        for (int w = 0; w < 8; w++) wpre += (w < wid) ? s_warp[w] : 0;
        offset = wpre + excl;
    }

    // Emit dense fp16 row.
    const float4* s4 = reinterpret_cast<const float4*>(sign_matrix + (size_t)row * INN);
    uint64_t* dst = reinterpret_cast<uint64_t*>(g_W + (size_t)row * INN);
    int cnt = 0;
#pragma unroll
    for (int j = 0; j < 4; j++) {
        float4 sg = s4[tid * 4 + j];
        const float* sp = reinterpret_cast<const float*>(&sg);
        __half h[4];
#pragma unroll
        for (int e = 0; e < 4; e++) {
            uint32_t k = keys[j * 4 + e];
            bool sel = false;
            if (k > P) sel = true;
            else if (k == P) {
                sel = common ? true : ((offset + cnt) < sel_ties);
                cnt++;
            }
            float f = fkey_inv(k);
            h[e] = __float2half(sel ? expf(f) * sp[e] : 0.0f);
        }
        dst[tid * 4 + j] = *reinterpret_cast<const uint64_t*>(h);
    }
}

// ===========================================================================
// Kernel C: mma.sync GEMM with mbarrier pipeline AND stage-boundary frag
// pipelining: the full-wait for stage it+1 and its kstep-0 ldmatrix loads are
// issued at ks==3 of stage it, BEFORE its final mma group, so next-stage ldsm
// latency overlaps the trailing HMMAs instead of being exposed.
// Block tile 128x256, BK=64, 4-stage ring; 256 threads = 8 warps (2x4),
// warp tile 64x64, fragments double-buffered across k-steps.
// full[s]: count 256 (cp.async.mbarrier.arrive.noinc per thread).
// empty[s]: count 8 (one arrive per warp at ks==2, after its last ldsm).
// Smem rows 144 B (128 data + 16 pad) => conflict-free ldmatrix.
// ===========================================================================
#define BM 128
#define BN 256
#define BK 64
#define NSTAGE 4
#define ROWB 144
#define A_STAGE (BM * ROWB)                 // 18432
#define B_STAGE (BN * ROWB)                 // 36864
#define STAGE_BYTES (A_STAGE + B_STAGE)     // 55296
#define SMEM_TOTAL (1024 + NSTAGE * STAGE_BYTES)   // 222208
#define NITER (INN / BK)                    // 64

__device__ __forceinline__ void load_stage(int s, int tid, int m0, int n0, uint32_t tile0) {
    uint32_t aS = tile0 + (uint32_t)(s & (NSTAGE - 1)) * STAGE_BYTES;
    uint32_t bS = aS + A_STAGE;
    const __half* aG = g_X + (size_t)m0 * INN + s * BK;
    const __half* bG = g_W + (size_t)n0 * INN + s * BK;
#pragma unroll
    for (int i = 0; i < 4; i++) {            // A: 128 rows x 8 chunks of 16 B
        int t = tid + i * 256;
        int r = t >> 3, c = t & 7;
        cp16(aS + r * ROWB + c * 16, aG + (size_t)r * INN + c * 8);
    }
#pragma unroll
    for (int i = 0; i < 8; i++) {            // B: 256 rows x 8 chunks of 16 B
        int t = tid + i * 256;
        int r = t >> 3, c = t & 7;
        cp16(bS + r * ROWB + c * 16, bG + (size_t)r * INN + c * 8);
    }
}

__device__ __forceinline__ void load_frags(uint32_t aS, uint32_t bS, uint32_t kb,
                                           uint32_t a_row, uint32_t a_kof,
                                           uint32_t b_row, uint32_t b_kof,
                                           uint32_t afr[4][4], uint32_t bfr[8][2]) {
#pragma unroll
    for (int mt = 0; mt < 4; mt++)
        ldmat_x4(afr[mt][0], afr[mt][1], afr[mt][2], afr[mt][3],
                 aS + (a_row + mt * 16) * ROWB + kb + a_kof);
#pragma unroll
    for (int p = 0; p < 4; p++) {
        uint32_t r0, r1, r2, r3;
        ldmat_x4(r0, r1, r2, r3, bS + (b_row + p * 16) * ROWB + kb + b_kof);
        bfr[2 * p][0] = r0;     bfr[2 * p][1] = r1;
        bfr[2 * p + 1][0] = r2; bfr[2 * p + 1][1] = r3;
    }
}

__global__ void __launch_bounds__(256, 1) gemm_kernel(float* __restrict__ out) {
    extern __shared__ char smem[];
    const uint32_t sbase = smem_u32(smem);
    const int tid  = threadIdx.x;
    const int lane = tid & 31;
    const int wid  = tid >> 5;
    const int m0 = blockIdx.x * BM;
    const int n0 = blockIdx.y * BN;
    const int wm = (wid & 1) * 64;
    const int wn = (wid >> 1) * 64;

    const uint32_t TILE0 = sbase + 1024;
#define FULLB(i)  (sbase + (uint32_t)(i) * 8)
#define EMPTYB(i) (sbase + 32 + (uint32_t)(i) * 8)

    if (tid == 0) {
#pragma unroll
        for (int i = 0; i < NSTAGE; i++) {
            MBARRIER_INIT(FULLB(i), 256);
            MBARRIER_INIT(EMPTYB(i), 8);
        }
    }
    __syncthreads();

    float acc[4][8][4];
#pragma unroll
    for (int mt = 0; mt < 4; mt++)
#pragma unroll
        for (int nt = 0; nt < 8; nt++)
#pragma unroll
            for (int i = 0; i < 4; i++) acc[mt][nt][i] = 0.0f;

    // Prologue: stages 0..NSTAGE-2 in flight.
#pragma unroll
    for (int s = 0; s < NSTAGE - 1; s++) {
        load_stage(s, tid, m0, n0, TILE0);
        CP_MBAR_ARRIVE(FULLB(s));
    }

    const uint32_t a_row = wm + (lane & 15);
    const uint32_t a_kof = (uint32_t)(lane >> 4) * 16;
    const uint32_t b_row = wn + (lane & 7) + ((lane >> 4) << 3);
    const uint32_t b_kof = (uint32_t)((lane >> 3) & 1) * 16;

    uint32_t afr[2][4][4], bfr[2][8][2];

    // Pre-wait stage 0 and load its kstep-0 fragments.
    MBARRIER_WAIT_PARITY(FULLB(0), 0);
    load_frags(TILE0, TILE0 + A_STAGE, 0, a_row, a_kof, b_row, b_kof, afr[0], bfr[0]);

#pragma unroll 1
    for (int it = 0; it < NITER; it++) {
        // Produce stage it + NSTAGE - 1.
        int ps = it + NSTAGE - 1;
        if (ps < NITER) {
            if (ps >= NSTAGE) {
                MBARRIER_WAIT_PARITY(EMPTYB(ps & (NSTAGE - 1)),
                                     (uint32_t)(((ps >> 2) - 1) & 1));
            }
            load_stage(ps, tid, m0, n0, TILE0);
            CP_MBAR_ARRIVE(FULLB(ps & (NSTAGE - 1)));
        }

        uint32_t aS = TILE0 + (uint32_t)(it & (NSTAGE - 1)) * STAGE_BYTES;
        uint32_t bS = aS + A_STAGE;

#pragma unroll
        for (int ks = 0; ks < 4; ks++) {
            if (ks < 3) {
                // Prefetch next kstep of this stage.
                load_frags(aS, bS, (uint32_t)(ks + 1) * 32, a_row, a_kof, b_row, b_kof,
                           afr[(ks + 1) & 1], bfr[(ks + 1) & 1]);
                if (ks == 2 && lane == 0) {
                    // Last ldsm of stage `it` issued — release the slot.
                    MBARRIER_ARRIVE(EMPTYB(it & (NSTAGE - 1)));
                }
            } else if (it + 1 < NITER) {
                // Stage boundary: wait next stage + load its kstep-0 frags
                // BEFORE the final mma group, hiding ldsm latency under HMMAs.
                MBARRIER_WAIT_PARITY(FULLB((it + 1) & (NSTAGE - 1)),
                                     (uint32_t)(((it + 1) >> 2) & 1));
                uint32_t aN = TILE0 + (uint32_t)((it + 1) & (NSTAGE - 1)) * STAGE_BYTES;
                load_frags(aN, aN + A_STAGE, 0, a_row, a_kof, b_row, b_kof,
                           afr[0], bfr[0]);
            }
            uint32_t (*af)[4] = afr[ks & 1];
            uint32_t (*bf)[2] = bfr[ks & 1];
#pragma unroll
            for (int mt = 0; mt < 4; mt++)
#pragma unroll
                for (int nt = 0; nt < 8; nt++)
                    mma16816(acc[mt][nt], af[mt], bf[nt]);
        }
    }

    // Epilogue.
    const int er = lane >> 2;
    const int ec = (lane & 3) * 2;
#pragma unroll
    for (int mt = 0; mt < 4; mt++) {
        int m = m0 + wm + mt * 16 + er;
#pragma unroll
        for (int nt = 0; nt < 8; nt++) {
            int n = n0 + wn + nt * 8 + ec;
            float2* p0 = reinterpret_cast<float2*>(out + (size_t)m * OUTN + n);
            float2* p1 = reinterpret_cast<float2*>(out + (size_t)(m + 8) * OUTN + n);
            *p0 = make_float2(acc[mt][nt][0], acc[mt][nt][1]);
            *p1 = make_float2(acc[mt][nt][2], acc[mt][nt][3]);
        }
    }
}

// ===========================================================================
extern "C" void kernel_launch(void* const* d_in, const int* in_sizes, int n_in,
                              void* d_out, int out_size) {
    const float* x      = (const float*)d_in[0];
    const float* pre_w  = (const float*)d_in[1];
    const float* sign_m = (const float*)d_in[2];
    float* out = (float*)d_out;

    cudaFuncSetAttribute(gemm_kernel, cudaFuncAttributeMaxDynamicSharedMemorySize, SMEM_TOTAL);

    prep_kernel<<<OUTN + CONV_BLKS, 256>>>(pre_w, sign_m, x);
    gemm_kernel<<<dim3(BATCH / BM, OUTN / BN), 256, SMEM_TOTAL>>>(out);
}

// round 11
// speedup vs baseline: 1.0903x; 1.0086x over previous
#include <cuda_runtime.h>
#include <cuda_fp16.h>
#include <cstdint>

#define INN   4096
#define OUTN  4096
#define BATCH 8192
#define KSEL  64

// Dense fp16 weight + fp16 activations (device-global scratch; no runtime alloc).
__device__ __align__(16) __half g_W[(size_t)OUTN * INN];   // 32 MB
__device__ __align__(16) __half g_X[(size_t)BATCH * INN];  // 64 MB

// ===========================================================================
// Helpers
// ===========================================================================
__device__ __forceinline__ uint32_t smem_u32(const void* p) {
    uint32_t a;
    asm("{ .reg .u64 t; cvta.to.shared.u64 t, %1; cvt.u32.u64 %0, t; }" : "=r"(a) : "l"(p));
    return a;
}
__device__ __forceinline__ void cp16(uint32_t dst, const void* src) {
    asm volatile("cp.async.cg.shared.global [%0], [%1], 16;" :: "r"(dst), "l"(src));
}
__device__ __forceinline__ void ldmat_x4(uint32_t& r0, uint32_t& r1, uint32_t& r2,
                                         uint32_t& r3, uint32_t addr) {
    asm volatile("ldmatrix.sync.aligned.m8n8.x4.shared.b16 {%0,%1,%2,%3}, [%4];"
                 : "=r"(r0), "=r"(r1), "=r"(r2), "=r"(r3) : "r"(addr));
}
__device__ __forceinline__ void mma16816(float* c, const uint32_t* a, const uint32_t* b) {
    asm volatile(
        "mma.sync.aligned.m16n8k16.row.col.f32.f16.f16.f32 "
        "{%0,%1,%2,%3}, {%4,%5,%6,%7}, {%8,%9}, {%0,%1,%2,%3};"
        : "+f"(c[0]), "+f"(c[1]), "+f"(c[2]), "+f"(c[3])
        : "r"(a[0]), "r"(a[1]), "r"(a[2]), "r"(a[3]), "r"(b[0]), "r"(b[1]));
}

#define MBARRIER_INIT(addr, cnt) \
    asm volatile("mbarrier.init.shared.b64 [%0], %1;" :: "r"(addr), "r"((uint32_t)(cnt)) : "memory")
#define MBARRIER_ARRIVE(addr) \
    asm volatile("mbarrier.arrive.shared.b64 _, [%0];" :: "r"(addr) : "memory")
#define CP_MBAR_ARRIVE(addr) \
    asm volatile("cp.async.mbarrier.arrive.noinc.shared.b64 [%0];" :: "r"(addr) : "memory")
#define MBARRIER_WAIT_PARITY(addr, par) do {                                          \
    uint32_t _m = (addr); uint32_t _p = (par); uint32_t _d;                           \
    asm volatile("{ .reg .pred p; mbarrier.try_wait.parity.acquire.cta.shared::cta.b64 p, [%1], %2; selp.b32 %0,1,0,p; }" \
        : "=r"(_d) : "r"(_m), "r"(_p) : "memory");                                    \
    if (!_d) {                                                                        \
        asm volatile("{ .reg .pred P1; WL_%=: mbarrier.try_wait.parity.acquire.cta.shared::cta.b64 P1, [%0], %1, 0x989680; @P1 bra.uni WD_%=; bra.uni WL_%=; WD_%=: }" \
            :: "r"(_m), "r"(_p) : "memory");                                          \
    }                                                                                 \
} while (0)

// Monotonic float -> uint32 key (order-preserving), and its inverse.
__device__ __forceinline__ uint32_t fkey(float f) {
    uint32_t u = __float_as_uint(f);
    return (u & 0x80000000u) ? ~u : (u | 0x80000000u);
}
__device__ __forceinline__ float fkey_inv(uint32_t k) {
    uint32_t u = (k & 0x80000000u) ? (k & 0x7FFFFFFFu) : ~k;
    return __uint_as_float(u);
}

// ===========================================================================
// Kernel A (fused): blocks [0, OUTN) select top-K per row and emit a dense
// fp16 weight row; blocks [OUTN, OUTN+CONV_BLKS) convert x fp32 -> fp16.
//
// Select: 12 block-wide radix-search iterations, then compact the <=256
// surviving candidates to smem and let warp 0 finish the remaining 20 bits
// barrier-free (fallback to block-wide loop if survivors > 256). Ties are
// resolved by an index threshold T (select iff key>P || (key==P && idx<=T)),
// matching jax.lax.top_k exactly. Emit gathers sign_matrix only at selected
// positions (64/row) instead of reading the full row.
// ===========================================================================
#define CONV_BLKS 4096
#define CAP 256

__global__ void __launch_bounds__(256) prep_kernel(const float* __restrict__ pre_w,
                                                   const float* __restrict__ sign_matrix,
                                                   const float* __restrict__ x) {
    const int tid = threadIdx.x;

    if (blockIdx.x >= OUTN) {
        // ---- convert x chunk ----
        int cb = blockIdx.x - OUTN;
        const float4* x4 = reinterpret_cast<const float4*>(x);
        __half2* dst = reinterpret_cast<__half2*>(g_X);
#pragma unroll
        for (int i = 0; i < 8; i++) {
            size_t v = (size_t)cb * 2048 + i * 256 + tid;
            float4 d = x4[v];
            dst[v * 2 + 0] = __floats2half2_rn(d.x, d.y);
            dst[v * 2 + 1] = __floats2half2_rn(d.z, d.w);
        }
        return;
    }

    __shared__ int s_warp[8];
    __shared__ uint32_t s_ckey[CAP];
    __shared__ uint16_t s_cpos[CAP];
    __shared__ int s_cnt;
    __shared__ uint32_t s_P, s_T;

    const int row  = blockIdx.x;
    const int lane = tid & 31;
    const int wid  = tid >> 5;

    const float4* w4 = reinterpret_cast<const float4*>(pre_w + (size_t)row * INN);

    uint32_t keys[16];
#pragma unroll
    for (int j = 0; j < 4; j++) {
        float4 v = w4[tid * 4 + j];
        keys[j * 4 + 0] = fkey(v.x);
        keys[j * 4 + 1] = fkey(v.y);
        keys[j * 4 + 2] = fkey(v.z);
        keys[j * 4 + 3] = fkey(v.w);
    }

    // Phase 1: 12 block-wide iterations (bits 31..20).
    uint32_t P = 0;
    int cnt_ge = INN;
#pragma unroll 1
    for (int bit = 31; bit >= 20; bit--) {
        uint32_t trial = P | (1u << bit);
        unsigned c = 0;
#pragma unroll
        for (int e = 0; e < 16; e++) c += (keys[e] >= trial);
        c = __reduce_add_sync(0xFFFFFFFFu, c);
        if (lane == 0) s_warp[wid] = (int)c;
        __syncthreads();
        int total = s_warp[0] + s_warp[1] + s_warp[2] + s_warp[3]
                  + s_warp[4] + s_warp[5] + s_warp[6] + s_warp[7];
        if (total >= KSEL) { P = trial; cnt_ge = total; }
        __syncthreads();
    }

    const bool fast = (cnt_ge <= CAP);
    uint32_t T = 4095;

    if (fast) {
        // Compact survivors (key >= P) into smem.
        if (tid == 0) s_cnt = 0;
        __syncthreads();
#pragma unroll
        for (int e = 0; e < 16; e++) {
            if (keys[e] >= P) {
                int p = atomicAdd(&s_cnt, 1);
                s_ckey[p] = keys[e];
                s_cpos[p] = (uint16_t)(tid * 16 + e);
            }
        }
        __syncthreads();

        if (wid == 0) {
            const int n = s_cnt;
            uint32_t ck[8];
            uint16_t cp[8];
            bool     cv[8];
#pragma unroll
            for (int j = 0; j < 8; j++) {
                int i = lane + j * 32;
                cv[j] = (i < n);
                ck[j] = cv[j] ? s_ckey[i] : 0u;
                cp[j] = cv[j] ? s_cpos[i] : (uint16_t)0;
            }
            // Finish bits 19..0 barrier-free.
            uint32_t Pl = P;
#pragma unroll 1
            for (int bit = 19; bit >= 0; bit--) {
                uint32_t trial = Pl | (1u << bit);
                unsigned c = 0;
#pragma unroll
                for (int j = 0; j < 8; j++) c += (cv[j] && ck[j] >= trial);
                c = __reduce_add_sync(0xFFFFFFFFu, c);
                if (c >= KSEL) Pl = trial;
            }
            // gt / eq totals.
            unsigned gt = 0, eq = 0;
#pragma unroll
            for (int j = 0; j < 8; j++) {
                gt += (cv[j] && ck[j] > Pl);
                eq += (cv[j] && ck[j] == Pl);
            }
            unsigned packed = __reduce_add_sync(0xFFFFFFFFu, (gt << 16) | eq);
            int total_gt = (int)(packed >> 16);
            int total_eq = (int)(packed & 0xFFFFu);
            int sel_ties = KSEL - total_gt;
            uint32_t Tl = 4095;
            if (total_eq != sel_ties) {
                // k-th smallest tie index: max T with count(tie && pos < T) < sel_ties.
                Tl = 0;
#pragma unroll 1
                for (int bit = 11; bit >= 0; bit--) {
                    uint32_t trial = Tl | (1u << bit);
                    unsigned c = 0;
#pragma unroll
                    for (int j = 0; j < 8; j++)
                        c += (cv[j] && ck[j] == Pl && (uint32_t)cp[j] < trial);
                    c = __reduce_add_sync(0xFFFFFFFFu, c);
                    if ((int)c < sel_ties) Tl = trial;
                }
            }
            if (lane == 0) { s_P = Pl; s_T = Tl; }
        }
        __syncthreads();
        P = s_P;
        T = s_T;
    } else {
        // Fallback: block-wide for remaining 20 bits.
#pragma unroll 1
        for (int bit = 19; bit >= 0; bit--) {
            uint32_t trial = P | (1u << bit);
            unsigned c = 0;
#pragma unroll
            for (int e = 0; e < 16; e++) c += (keys[e] >= trial);
            c = __reduce_add_sync(0xFFFFFFFFu, c);
            if (lane == 0) s_warp[wid] = (int)c;
            __syncthreads();
            int total = s_warp[0] + s_warp[1] + s_warp[2] + s_warp[3]
                      + s_warp[4] + s_warp[5] + s_warp[6] + s_warp[7];
            if (total >= KSEL) P = trial;
            __syncthreads();
        }
        // gt/eq totals.
        unsigned gt = 0, eq = 0;
#pragma unroll
        for (int e = 0; e < 16; e++) {
            gt += (keys[e] > P);
            eq += (keys[e] == P);
        }
        unsigned packed = __reduce_add_sync(0xFFFFFFFFu, (gt << 16) | eq);
        if (lane == 0) s_warp[wid] = (int)packed;
        __syncthreads();
        unsigned tot = (unsigned)(s_warp[0] + s_warp[1] + s_warp[2] + s_warp[3]
                                + s_warp[4] + s_warp[5] + s_warp[6] + s_warp[7]);
        int total_gt = (int)(tot >> 16);
        int total_eq = (int)(tot & 0xFFFFu);
        int sel_ties = KSEL - total_gt;
        __syncthreads();
        if (total_eq != sel_ties) {
            // Block-wide 12-bit search on tie indices.
            T = 0;
#pragma unroll 1
            for (int bit = 11; bit >= 0; bit--) {
                uint32_t trial = T | (1u << bit);
                unsigned c = 0;
#pragma unroll
                for (int e = 0; e < 16; e++)
                    c += (keys[e] == P && (uint32_t)(tid * 16 + e) < trial);
                c = __reduce_add_sync(0xFFFFFFFFu, c);
                if (lane == 0) s_warp[wid] = (int)c;
                __syncthreads();
                int total = s_warp[0] + s_warp[1] + s_warp[2] + s_warp[3]
                          + s_warp[4] + s_warp[5] + s_warp[6] + s_warp[7];
                if (total < sel_ties) T = trial;
                __syncthreads();
            }
        }
    }

    // Emit dense fp16 row; gather sign only at selected positions.
    const float* srow = sign_matrix + (size_t)row * INN;
    uint64_t* dst = reinterpret_cast<uint64_t*>(g_W + (size_t)row * INN);
#pragma unroll
    for (int j = 0; j < 4; j++) {
        __half h[4];
#pragma unroll
        for (int e = 0; e < 4; e++) {
            uint32_t k = keys[j * 4 + e];
            uint32_t idx = (uint32_t)(tid * 16 + j * 4 + e);
            bool sel = (k > P) || (k == P && idx <= T);
            float v = 0.0f;
            if (sel) v = expf(fkey_inv(k)) * srow[idx];
            h[e] = __float2half(v);
        }
        dst[tid * 4 + j] = *reinterpret_cast<const uint64_t*>(h);
    }
}

// ===========================================================================
// Kernel C: mma.sync GEMM (R10 winner, unchanged). out[B,OUT] = g_X @ g_W^T.
// Block tile 128x256, BK=64, 4-stage mbarrier ring; 256 threads = 8 warps
// (2x4), warp tile 64x64, frag double-buffer + stage-boundary prefetch.
// ===========================================================================
#define BM 128
#define BN 256
#define BK 64
#define NSTAGE 4
#define ROWB 144
#define A_STAGE (BM * ROWB)                 // 18432
#define B_STAGE (BN * ROWB)                 // 36864
#define STAGE_BYTES (A_STAGE + B_STAGE)     // 55296
#define SMEM_TOTAL (1024 + NSTAGE * STAGE_BYTES)   // 222208
#define NITER (INN / BK)                    // 64

__device__ __forceinline__ void load_stage(int s, int tid, int m0, int n0, uint32_t tile0) {
    uint32_t aS = tile0 + (uint32_t)(s & (NSTAGE - 1)) * STAGE_BYTES;
    uint32_t bS = aS + A_STAGE;
    const __half* aG = g_X + (size_t)m0 * INN + s * BK;
    const __half* bG = g_W + (size_t)n0 * INN + s * BK;
#pragma unroll
    for (int i = 0; i < 4; i++) {            // A: 128 rows x 8 chunks of 16 B
        int t = tid + i * 256;
        int r = t >> 3, c = t & 7;
        cp16(aS + r * ROWB + c * 16, aG + (size_t)r * INN + c * 8);
    }
#pragma unroll
    for (int i = 0; i < 8; i++) {            // B: 256 rows x 8 chunks of 16 B
        int t = tid + i * 256;
        int r = t >> 3, c = t & 7;
        cp16(bS + r * ROWB + c * 16, bG + (size_t)r * INN + c * 8);
    }
}

__device__ __forceinline__ void load_frags(uint32_t aS, uint32_t bS, uint32_t kb,
                                           uint32_t a_row, uint32_t a_kof,
                                           uint32_t b_row, uint32_t b_kof,
                                           uint32_t afr[4][4], uint32_t bfr[8][2]) {
#pragma unroll
    for (int mt = 0; mt < 4; mt++)
        ldmat_x4(afr[mt][0], afr[mt][1], afr[mt][2], afr[mt][3],
                 aS + (a_row + mt * 16) * ROWB + kb + a_kof);
#pragma unroll
    for (int p = 0; p < 4; p++) {
        uint32_t r0, r1, r2, r3;
        ldmat_x4(r0, r1, r2, r3, bS + (b_row + p * 16) * ROWB + kb + b_kof);
        bfr[2 * p][0] = r0;     bfr[2 * p][1] = r1;
        bfr[2 * p + 1][0] = r2; bfr[2 * p + 1][1] = r3;
    }
}

__global__ void __launch_bounds__(256, 1) gemm_kernel(float* __restrict__ out) {
    extern __shared__ char smem[];
    const uint32_t sbase = smem_u32(smem);
    const int tid  = threadIdx.x;
    const int lane = tid & 31;
    const int wid  = tid >> 5;
    const int m0 = blockIdx.x * BM;
    const int n0 = blockIdx.y * BN;
    const int wm = (wid & 1) * 64;
    const int wn = (wid >> 1) * 64;

    const uint32_t TILE0 = sbase + 1024;
#define FULLB(i)  (sbase + (uint32_t)(i) * 8)
#define EMPTYB(i) (sbase + 32 + (uint32_t)(i) * 8)

    if (tid == 0) {
#pragma unroll
        for (int i = 0; i < NSTAGE; i++) {
            MBARRIER_INIT(FULLB(i), 256);
            MBARRIER_INIT(EMPTYB(i), 8);
        }
    }
    __syncthreads();

    float acc[4][8][4];
#pragma unroll
    for (int mt = 0; mt < 4; mt++)
#pragma unroll
        for (int nt = 0; nt < 8; nt++)
#pragma unroll
            for (int i = 0; i < 4; i++) acc[mt][nt][i] = 0.0f;

#pragma unroll
    for (int s = 0; s < NSTAGE - 1; s++) {
        load_stage(s, tid, m0, n0, TILE0);
        CP_MBAR_ARRIVE(FULLB(s));
    }

    const uint32_t a_row = wm + (lane & 15);
    const uint32_t a_kof = (uint32_t)(lane >> 4) * 16;
    const uint32_t b_row = wn + (lane & 7) + ((lane >> 4) << 3);
    const uint32_t b_kof = (uint32_t)((lane >> 3) & 1) * 16;

    uint32_t afr[2][4][4], bfr[2][8][2];

    MBARRIER_WAIT_PARITY(FULLB(0), 0);
    load_frags(TILE0, TILE0 + A_STAGE, 0, a_row, a_kof, b_row, b_kof, afr[0], bfr[0]);

#pragma unroll 1
    for (int it = 0; it < NITER; it++) {
        int ps = it + NSTAGE - 1;
        if (ps < NITER) {
            if (ps >= NSTAGE) {
                MBARRIER_WAIT_PARITY(EMPTYB(ps & (NSTAGE - 1)),
                                     (uint32_t)(((ps >> 2) - 1) & 1));
            }
            load_stage(ps, tid, m0, n0, TILE0);
            CP_MBAR_ARRIVE(FULLB(ps & (NSTAGE - 1)));
        }

        uint32_t aS = TILE0 + (uint32_t)(it & (NSTAGE - 1)) * STAGE_BYTES;
        uint32_t bS = aS + A_STAGE;

#pragma unroll
        for (int ks = 0; ks < 4; ks++) {
            if (ks < 3) {
                load_frags(aS, bS, (uint32_t)(ks + 1) * 32, a_row, a_kof, b_row, b_kof,
                           afr[(ks + 1) & 1], bfr[(ks + 1) & 1]);
                if (ks == 2 && lane == 0) {
                    MBARRIER_ARRIVE(EMPTYB(it & (NSTAGE - 1)));
                }
            } else if (it + 1 < NITER) {
                MBARRIER_WAIT_PARITY(FULLB((it + 1) & (NSTAGE - 1)),
                                     (uint32_t)(((it + 1) >> 2) & 1));
                uint32_t aN = TILE0 + (uint32_t)((it + 1) & (NSTAGE - 1)) * STAGE_BYTES;
                load_frags(aN, aN + A_STAGE, 0, a_row, a_kof, b_row, b_kof,
                           afr[0], bfr[0]);
            }
            uint32_t (*af)[4] = afr[ks & 1];
            uint32_t (*bf)[2] = bfr[ks & 1];
#pragma unroll
            for (int mt = 0; mt < 4; mt++)
#pragma unroll
                for (int nt = 0; nt < 8; nt++)
                    mma16816(acc[mt][nt], af[mt], bf[nt]);
        }
    }

    // Epilogue.
    const int er = lane >> 2;
    const int ec = (lane & 3) * 2;
#pragma unroll
    for (int mt = 0; mt < 4; mt++) {
        int m = m0 + wm + mt * 16 + er;
#pragma unroll
        for (int nt = 0; nt < 8; nt++) {
            int n = n0 + wn + nt * 8 + ec;
            float2* p0 = reinterpret_cast<float2*>(out + (size_t)m * OUTN + n);
            float2* p1 = reinterpret_cast<float2*>(out + (size_t)(m + 8) * OUTN + n);
            *p0 = make_float2(acc[mt][nt][0], acc[mt][nt][1]);
            *p1 = make_float2(acc[mt][nt][2], acc[mt][nt][3]);
        }
    }
}

// ===========================================================================
extern "C" void kernel_launch(void* const* d_in, const int* in_sizes, int n_in,
                              void* d_out, int out_size) {
    const float* x      = (const float*)d_in[0];
    const float* pre_w  = (const float*)d_in[1];
    const float* sign_m = (const float*)d_in[2];
    float* out = (float*)d_out;

    cudaFuncSetAttribute(gemm_kernel, cudaFuncAttributeMaxDynamicSharedMemorySize, SMEM_TOTAL);

    prep_kernel<<<OUTN + CONV_BLKS, 256>>>(pre_w, sign_m, x);
    gemm_kernel<<<dim3(BATCH / BM, OUTN / BN), 256, SMEM_TOTAL>>>(out);
}

// round 13
// speedup vs baseline: 1.1530x; 1.0575x over previous
#include <cuda_runtime.h>
#include <cuda_fp16.h>
#include <cstdint>

#define INN   4096
#define OUTN  4096
#define BATCH 8192
#define KSEL  64

// Dense fp16 weight + fp16 activations (device-global scratch; no runtime alloc).
__device__ __align__(16) __half g_W[(size_t)OUTN * INN];   // 32 MB
__device__ __align__(16) __half g_X[(size_t)BATCH * INN];  // 64 MB

// ===========================================================================
// Helpers
// ===========================================================================
__device__ __forceinline__ uint32_t smem_u32(const void* p) {
    uint32_t a;
    asm("{ .reg .u64 t; cvta.to.shared.u64 t, %1; cvt.u32.u64 %0, t; }" : "=r"(a) : "l"(p));
    return a;
}
__device__ __forceinline__ void cp16(uint32_t dst, const void* src) {
    asm volatile("cp.async.cg.shared.global [%0], [%1], 16;" :: "r"(dst), "l"(src));
}
__device__ __forceinline__ void ldmat_x4(uint32_t& r0, uint32_t& r1, uint32_t& r2,
                                         uint32_t& r3, uint32_t addr) {
    asm volatile("ldmatrix.sync.aligned.m8n8.x4.shared.b16 {%0,%1,%2,%3}, [%4];"
                 : "=r"(r0), "=r"(r1), "=r"(r2), "=r"(r3) : "r"(addr));
}
__device__ __forceinline__ void mma16816(float* c, const uint32_t* a, const uint32_t* b) {
    asm volatile(
        "mma.sync.aligned.m16n8k16.row.col.f32.f16.f16.f32 "
        "{%0,%1,%2,%3}, {%4,%5,%6,%7}, {%8,%9}, {%0,%1,%2,%3};"
        : "+f"(c[0]), "+f"(c[1]), "+f"(c[2]), "+f"(c[3])
        : "r"(a[0]), "r"(a[1]), "r"(a[2]), "r"(a[3]), "r"(b[0]), "r"(b[1]));
}
__device__ __forceinline__ uint32_t h2_bits(__half2 h) {
    uint32_t u;
    *reinterpret_cast<__half2*>(&u) = h;
    return u;
}

#define MBARRIER_INIT(addr, cnt) \
    asm volatile("mbarrier.init.shared.b64 [%0], %1;" :: "r"(addr), "r"((uint32_t)(cnt)) : "memory")
#define MBARRIER_ARRIVE(addr) \
    asm volatile("mbarrier.arrive.shared.b64 _, [%0];" :: "r"(addr) : "memory")
#define CP_MBAR_ARRIVE(addr) \
    asm volatile("cp.async.mbarrier.arrive.noinc.shared.b64 [%0];" :: "r"(addr) : "memory")
#define MBARRIER_WAIT_PARITY(addr, par) do {                                          \
    uint32_t _m = (addr); uint32_t _p = (par); uint32_t _d;                           \
    asm volatile("{ .reg .pred p; mbarrier.try_wait.parity.acquire.cta.shared::cta.b64 p, [%1], %2; selp.b32 %0,1,0,p; }" \
        : "=r"(_d) : "r"(_m), "r"(_p) : "memory");                                    \
    if (!_d) {                                                                        \
        asm volatile("{ .reg .pred P1; WL_%=: mbarrier.try_wait.parity.acquire.cta.shared::cta.b64 P1, [%0], %1, 0x989680; @P1 bra.uni WD_%=; bra.uni WL_%=; WD_%=: }" \
            :: "r"(_m), "r"(_p) : "memory");                                          \
    }                                                                                 \
} while (0)

// Monotonic float -> uint32 key (order-preserving), and its inverse.
__device__ __forceinline__ uint32_t fkey(float f) {
    uint32_t u = __float_as_uint(f);
    return (u & 0x80000000u) ? ~u : (u | 0x80000000u);
}
__device__ __forceinline__ float fkey_inv(uint32_t k) {
    uint32_t u = (k & 0x80000000u) ? (k & 0x7FFFFFFFu) : ~k;
    return __uint_as_float(u);
}

// ===========================================================================
// Kernel A (fused): blocks [0, OUTN) select top-K per row and emit a dense
// fp16 weight row; blocks [OUTN, OUTN+CONV_BLKS) convert x fp32 -> fp16
// (32 B per thread-iteration, uint4 stores).
// ===========================================================================
#define CONV_BLKS 4096
#define CAP 256

__global__ void __launch_bounds__(256) prep_kernel(const float* __restrict__ pre_w,
                                                   const float* __restrict__ sign_matrix,
                                                   const float* __restrict__ x) {
    const int tid = threadIdx.x;

    if (blockIdx.x >= OUTN) {
        // ---- convert x chunk: 4 iters x 256 threads x 32 B ----
        int cb = blockIdx.x - OUTN;
        const float4* x4 = reinterpret_cast<const float4*>(x);
        uint4* dst = reinterpret_cast<uint4*>(g_X);
#pragma unroll
        for (int i = 0; i < 4; i++) {
            size_t v = (size_t)cb * 1024 + i * 256 + tid;  // 32-byte units
            float4 d0 = x4[v * 2 + 0];
            float4 d1 = x4[v * 2 + 1];
            uint4 o;
            o.x = h2_bits(__floats2half2_rn(d0.x, d0.y));
            o.y = h2_bits(__floats2half2_rn(d0.z, d0.w));
            o.z = h2_bits(__floats2half2_rn(d1.x, d1.y));
            o.w = h2_bits(__floats2half2_rn(d1.z, d1.w));
            dst[v] = o;
        }
        return;
    }

    __shared__ int s_warp[8];
    __shared__ uint32_t s_ckey[CAP];
    __shared__ uint16_t s_cpos[CAP];
    __shared__ int s_cnt;
    __shared__ uint32_t s_P, s_T;

    const int row  = blockIdx.x;
    const int lane = tid & 31;
    const int wid  = tid >> 5;

    const float4* w4 = reinterpret_cast<const float4*>(pre_w + (size_t)row * INN);

    uint32_t keys[16];
#pragma unroll
    for (int j = 0; j < 4; j++) {
        float4 v = w4[tid * 4 + j];
        keys[j * 4 + 0] = fkey(v.x);
        keys[j * 4 + 1] = fkey(v.y);
        keys[j * 4 + 2] = fkey(v.z);
        keys[j * 4 + 3] = fkey(v.w);
    }

    // Phase 1: 12 block-wide iterations (bits 31..20).
    uint32_t P = 0;
    int cnt_ge = INN;
#pragma unroll 1
    for (int bit = 31; bit >= 20; bit--) {
        uint32_t trial = P | (1u << bit);
        unsigned c = 0;
#pragma unroll
        for (int e = 0; e < 16; e++) c += (keys[e] >= trial);
        c = __reduce_add_sync(0xFFFFFFFFu, c);
        if (lane == 0) s_warp[wid] = (int)c;
        __syncthreads();
        int total = s_warp[0] + s_warp[1] + s_warp[2] + s_warp[3]
                  + s_warp[4] + s_warp[5] + s_warp[6] + s_warp[7];
        if (total >= KSEL) { P = trial; cnt_ge = total; }
        __syncthreads();
    }

    const bool fast = (cnt_ge <= CAP);
    uint32_t T = 4095;

    if (fast) {
        // Compact survivors (key >= P) into smem.
        if (tid == 0) s_cnt = 0;
        __syncthreads();
#pragma unroll
        for (int e = 0; e < 16; e++) {
            if (keys[e] >= P) {
                int p = atomicAdd(&s_cnt, 1);
                s_ckey[p] = keys[e];
                s_cpos[p] = (uint16_t)(tid * 16 + e);
            }
        }
        __syncthreads();

        if (wid == 0) {
            const int n = s_cnt;
            uint32_t ck[8];
            uint16_t cp[8];
            bool     cv[8];
#pragma unroll
            for (int j = 0; j < 8; j++) {
                int i = lane + j * 32;
                cv[j] = (i < n);
                ck[j] = cv[j] ? s_ckey[i] : 0u;
                cp[j] = cv[j] ? s_cpos[i] : (uint16_t)0;
            }
            // Finish bits 19..0 barrier-free.
            uint32_t Pl = P;
#pragma unroll 1
            for (int bit = 19; bit >= 0; bit--) {
                uint32_t trial = Pl | (1u << bit);
                unsigned c = 0;
#pragma unroll
                for (int j = 0; j < 8; j++) c += (cv[j] && ck[j] >= trial);
                c = __reduce_add_sync(0xFFFFFFFFu, c);
                if (c >= KSEL) Pl = trial;
            }
            // gt / eq totals.
            unsigned gt = 0, eq = 0;
#pragma unroll
            for (int j = 0; j < 8; j++) {
                gt += (cv[j] && ck[j] > Pl);
                eq += (cv[j] && ck[j] == Pl);
            }
            unsigned packed = __reduce_add_sync(0xFFFFFFFFu, (gt << 16) | eq);
            int total_gt = (int)(packed >> 16);
            int total_eq = (int)(packed & 0xFFFFu);
            int sel_ties = KSEL - total_gt;
            uint32_t Tl = 4095;
            if (total_eq != sel_ties) {
                Tl = 0;
#pragma unroll 1
                for (int bit = 11; bit >= 0; bit--) {
                    uint32_t trial = Tl | (1u << bit);
                    unsigned c = 0;
#pragma unroll
                    for (int j = 0; j < 8; j++)
                        c += (cv[j] && ck[j] == Pl && (uint32_t)cp[j] < trial);
                    c = __reduce_add_sync(0xFFFFFFFFu, c);
                    if ((int)c < sel_ties) Tl = trial;
                }
            }
            if (lane == 0) { s_P = Pl; s_T = Tl; }
        }
        __syncthreads();
        P = s_P;
        T = s_T;
    } else {
        // Fallback: block-wide for remaining 20 bits.
#pragma unroll 1
        for (int bit = 19; bit >= 0; bit--) {
            uint32_t trial = P | (1u << bit);
            unsigned c = 0;
#pragma unroll
            for (int e = 0; e < 16; e++) c += (keys[e] >= trial);
            c = __reduce_add_sync(0xFFFFFFFFu, c);
            if (lane == 0) s_warp[wid] = (int)c;
            __syncthreads();
            int total = s_warp[0] + s_warp[1] + s_warp[2] + s_warp[3]
                      + s_warp[4] + s_warp[5] + s_warp[6] + s_warp[7];
            if (total >= KSEL) P = trial;
            __syncthreads();
        }
        unsigned gt = 0, eq = 0;
#pragma unroll
        for (int e = 0; e < 16; e++) {
            gt += (keys[e] > P);
            eq += (keys[e] == P);
        }
        unsigned packed = __reduce_add_sync(0xFFFFFFFFu, (gt << 16) | eq);
        if (lane == 0) s_warp[wid] = (int)packed;
        __syncthreads();
        unsigned tot = (unsigned)(s_warp[0] + s_warp[1] + s_warp[2] + s_warp[3]
                                + s_warp[4] + s_warp[5] + s_warp[6] + s_warp[7]);
        int total_gt = (int)(tot >> 16);
        int total_eq = (int)(tot & 0xFFFFu);
        int sel_ties = KSEL - total_gt;
        __syncthreads();
        if (total_eq != sel_ties) {
            T = 0;
#pragma unroll 1
            for (int bit = 11; bit >= 0; bit--) {
                uint32_t trial = T | (1u << bit);
                unsigned c = 0;
#pragma unroll
                for (int e = 0; e < 16; e++)
                    c += (keys[e] == P && (uint32_t)(tid * 16 + e) < trial);
                c = __reduce_add_sync(0xFFFFFFFFu, c);
                if (lane == 0) s_warp[wid] = (int)c;
                __syncthreads();
                int total = s_warp[0] + s_warp[1] + s_warp[2] + s_warp[3]
                          + s_warp[4] + s_warp[5] + s_warp[6] + s_warp[7];
                if (total < sel_ties) T = trial;
                __syncthreads();
            }
        }
    }

    // Emit dense fp16 row; gather sign only at selected positions.
    const float* srow = sign_matrix + (size_t)row * INN;
    uint64_t* dst = reinterpret_cast<uint64_t*>(g_W + (size_t)row * INN);
#pragma unroll
    for (int j = 0; j < 4; j++) {
        __half h[4];
#pragma unroll
        for (int e = 0; e < 4; e++) {
            uint32_t k = keys[j * 4 + e];
            uint32_t idx = (uint32_t)(tid * 16 + j * 4 + e);
            bool sel = (k > P) || (k == P && idx <= T);
            float v = 0.0f;
            if (sel) v = expf(fkey_inv(k)) * srow[idx];
            h[e] = __float2half(v);
        }
        dst[tid * 4 + j] = *reinterpret_cast<const uint64_t*>(h);
    }
}

// ===========================================================================
// Kernel C: mma.sync GEMM with mbarrier pipeline, stage-boundary frag
// prefetch, AND deferred producer phase (empty-wait + load_stage moved to
// the ks==1 slot so iteration entry is stall-free and slow-warp coupling
// gets 3 extra k-steps of slack).
// Block tile 128x256, BK=64, 4-stage ring; 256 threads = 8 warps (2x4),
// warp tile 64x64, fragments double-buffered across k-steps.
// ===========================================================================
#define BM 128
#define BN 256
#define BK 64
#define NSTAGE 4
#define ROWB 144
#define A_STAGE (BM * ROWB)                 // 18432
#define B_STAGE (BN * ROWB)                 // 36864
#define STAGE_BYTES (A_STAGE + B_STAGE)     // 55296
#define SMEM_TOTAL (1024 + NSTAGE * STAGE_BYTES)   // 222208
#define NITER (INN / BK)                    // 64

__device__ __forceinline__ void load_stage(int s, int tid, int m0, int n0, uint32_t tile0) {
    uint32_t aS = tile0 + (uint32_t)(s & (NSTAGE - 1)) * STAGE_BYTES;
    uint32_t bS = aS + A_STAGE;
    const __half* aG = g_X + (size_t)m0 * INN + s * BK;
    const __half* bG = g_W + (size_t)n0 * INN + s * BK;
#pragma unroll
    for (int i = 0; i < 4; i++) {            // A: 128 rows x 8 chunks of 16 B
        int t = tid + i * 256;
        int r = t >> 3, c = t & 7;
        cp16(aS + r * ROWB + c * 16, aG + (size_t)r * INN + c * 8);
    }
#pragma unroll
    for (int i = 0; i < 8; i++) {            // B: 256 rows x 8 chunks of 16 B
        int t = tid + i * 256;
        int r = t >> 3, c = t & 7;
        cp16(bS + r * ROWB + c * 16, bG + (size_t)r * INN + c * 8);
    }
}

__device__ __forceinline__ void load_frags(uint32_t aS, uint32_t bS, uint32_t kb,
                                           uint32_t a_row, uint32_t a_kof,
                                           uint32_t b_row, uint32_t b_kof,
                                           uint32_t afr[4][4], uint32_t bfr[8][2]) {
#pragma unroll
    for (int mt = 0; mt < 4; mt++)
        ldmat_x4(afr[mt][0], afr[mt][1], afr[mt][2], afr[mt][3],
                 aS + (a_row + mt * 16) * ROWB + kb + a_kof);
#pragma unroll
    for (int p = 0; p < 4; p++) {
        uint32_t r0, r1, r2, r3;
        ldmat_x4(r0, r1, r2, r3, bS + (b_row + p * 16) * ROWB + kb + b_kof);
        bfr[2 * p][0] = r0;     bfr[2 * p][1] = r1;
        bfr[2 * p + 1][0] = r2; bfr[2 * p + 1][1] = r3;
    }
}

__global__ void __launch_bounds__(256, 1) gemm_kernel(float* __restrict__ out) {
    extern __shared__ char smem[];
    const uint32_t sbase = smem_u32(smem);
    const int tid  = threadIdx.x;
    const int lane = tid & 31;
    const int wid  = tid >> 5;
    const int m0 = blockIdx.x * BM;
    const int n0 = blockIdx.y * BN;
    const int wm = (wid & 1) * 64;
    const int wn = (wid >> 1) * 64;

    const uint32_t TILE0 = sbase + 1024;
#define FULLB(i)  (sbase + (uint32_t)(i) * 8)
#define EMPTYB(i) (sbase + 32 + (uint32_t)(i) * 8)

    if (tid == 0) {
#pragma unroll
        for (int i = 0; i < NSTAGE; i++) {
            MBARRIER_INIT(FULLB(i), 256);
            MBARRIER_INIT(EMPTYB(i), 8);
        }
    }
    __syncthreads();

    float acc[4][8][4];
#pragma unroll
    for (int mt = 0; mt < 4; mt++)
#pragma unroll
        for (int nt = 0; nt < 8; nt++)
#pragma unroll
            for (int i = 0; i < 4; i++) acc[mt][nt][i] = 0.0f;

    // Prologue: stages 0..NSTAGE-2 in flight.
#pragma unroll
    for (int s = 0; s < NSTAGE - 1; s++) {
        load_stage(s, tid, m0, n0, TILE0);
        CP_MBAR_ARRIVE(FULLB(s));
    }

    const uint32_t a_row = wm + (lane & 15);
    const uint32_t a_kof = (uint32_t)(lane >> 4) * 16;
    const uint32_t b_row = wn + (lane & 7) + ((lane >> 4) << 3);
    const uint32_t b_kof = (uint32_t)((lane >> 3) & 1) * 16;

    uint32_t afr[2][4][4], bfr[2][8][2];

    // Pre-wait stage 0 and load its kstep-0 fragments.
    MBARRIER_WAIT_PARITY(FULLB(0), 0);
    load_frags(TILE0, TILE0 + A_STAGE, 0, a_row, a_kof, b_row, b_kof, afr[0], bfr[0]);

#pragma unroll 1
    for (int it = 0; it < NITER; it++) {
        uint32_t aS = TILE0 + (uint32_t)(it & (NSTAGE - 1)) * STAGE_BYTES;
        uint32_t bS = aS + A_STAGE;

#pragma unroll
        for (int ks = 0; ks < 4; ks++) {
            // Deferred producer: issue stage it+3 in the ks==1 slot.
            if (ks == 1) {
                int ps = it + NSTAGE - 1;
                if (ps < NITER) {
                    if (ps >= NSTAGE) {
                        MBARRIER_WAIT_PARITY(EMPTYB(ps & (NSTAGE - 1)),
                                             (uint32_t)(((ps >> 2) - 1) & 1));
                    }
                    load_stage(ps, tid, m0, n0, TILE0);
                    CP_MBAR_ARRIVE(FULLB(ps & (NSTAGE - 1)));
                }
            }
            if (ks < 3) {
                // Prefetch next kstep of this stage.
                load_frags(aS, bS, (uint32_t)(ks + 1) * 32, a_row, a_kof, b_row, b_kof,
                           afr[(ks + 1) & 1], bfr[(ks + 1) & 1]);
                if (ks == 2 && lane == 0) {
                    // Last ldsm of stage `it` issued — release the slot.
                    MBARRIER_ARRIVE(EMPTYB(it & (NSTAGE - 1)));
                }
            } else if (it + 1 < NITER) {
                // Stage boundary: wait next stage + load its kstep-0 frags
                // BEFORE the final mma group.
                MBARRIER_WAIT_PARITY(FULLB((it + 1) & (NSTAGE - 1)),
                                     (uint32_t)(((it + 1) >> 2) & 1));
                uint32_t aN = TILE0 + (uint32_t)((it + 1) & (NSTAGE - 1)) * STAGE_BYTES;
                load_frags(aN, aN + A_STAGE, 0, a_row, a_kof, b_row, b_kof,
                           afr[0], bfr[0]);
            }
            uint32_t (*af)[4] = afr[ks & 1];
            uint32_t (*bf)[2] = bfr[ks & 1];
#pragma unroll
            for (int mt = 0; mt < 4; mt++)
#pragma unroll
                for (int nt = 0; nt < 8; nt++)
                    mma16816(acc[mt][nt], af[mt], bf[nt]);
        }
    }

    // Epilogue.
    const int er = lane >> 2;
    const int ec = (lane & 3) * 2;
#pragma unroll
    for (int mt = 0; mt < 4; mt++) {
        int m = m0 + wm + mt * 16 + er;
#pragma unroll
        for (int nt = 0; nt < 8; nt++) {
            int n = n0 + wn + nt * 8 + ec;
            float2* p0 = reinterpret_cast<float2*>(out + (size_t)m * OUTN + n);
            float2* p1 = reinterpret_cast<float2*>(out + (size_t)(m + 8) * OUTN + n);
            *p0 = make_float2(acc[mt][nt][0], acc[mt][nt][1]);
            *p1 = make_float2(acc[mt][nt][2], acc[mt][nt][3]);
        }
    }
}

// ===========================================================================
extern "C" void kernel_launch(void* const* d_in, const int* in_sizes, int n_in,
                              void* d_out, int out_size) {
    const float* x      = (const float*)d_in[0];
    const float* pre_w  = (const float*)d_in[1];
    const float* sign_m = (const float*)d_in[2];
    float* out = (float*)d_out;

    cudaFuncSetAttribute(gemm_kernel, cudaFuncAttributeMaxDynamicSharedMemorySize, SMEM_TOTAL);

    prep_kernel<<<OUTN + CONV_BLKS, 256>>>(pre_w, sign_m, x);
    gemm_kernel<<<dim3(BATCH / BM, OUTN / BN), 256, SMEM_TOTAL>>>(out);
}